// round 3
// baseline (speedup 1.0000x reference)
#include <cuda_runtime.h>
#include <cuda_bf16.h>
#include <math.h>

// ---------------------------------------------------------------------------
// RTE forward (word-by-word attention entailment model), fp32.
// B=128, T=128, NDIM=512, EMB=300, G=3*NDIM=1536, VOCAB=50000.
//
// Strategy:
//   * Hoist all loop-invariant GEMMs out of the recurrences:
//       Gi_p/Gi_h  = E[tok] @ Wih^T + bih           (gather fused into GEMM)
//       Yw         = o_p @ W_y
//       hWh        = o_h @ W_h
//       gihp       = o_h @ mWih[:,512:]^T + m_bih
//   * Each sequential GRU step = ONE fused kernel: gate-packed Whh GEMM
//     (rows n*3+g) + gate nonlinearity + masked update.
//   * Attention step = 4 kernels: s-GEMM(+addend), alpha (tanh dot), softmax+
//     context, fused match-GRU step (two K=512 dots per gate).
// ---------------------------------------------------------------------------

#define B_   128
#define T_   128
#define N_   512
#define E_   300
#define G_   1536
#define TBN_ (T_ * B_)   // 16384

// ------------------------------- scratch (static device memory) ------------
__device__ float g_GiP[TBN_ * G_];     // premise input gates, [t*B+b][1536]
__device__ float g_GiH[TBN_ * G_];     // hypothesis input gates
__device__ float g_oP [TBN_ * N_];     // premise GRU outputs  [t][b][n]
__device__ float g_oH [TBN_ * N_];     // hypothesis GRU outputs
__device__ float g_Yw [TBN_ * N_];     // o_p @ W_y
__device__ float g_hWh[TBN_ * N_];     // o_h @ W_h
__device__ float g_gihp[TBN_ * G_];    // o_h @ mWih_h^T + m_bih
__device__ float g_h0[B_ * N_];        // hidden ping-pong
__device__ float g_h1[B_ * N_];
__device__ float g_r0[B_ * N_];        // match-GRU state ping-pong
__device__ float g_r1[B_ * N_];
__device__ float g_s  [B_ * N_];       // attention s per step
__device__ float g_alpha[B_ * T_];     // attention logits per step
__device__ float g_a  [B_ * N_];       // context vector per step
__device__ float g_maskP[T_ * B_];
__device__ float g_maskH[T_ * B_];
__device__ float g_WyT[N_ * N_];
__device__ float g_WhT[N_ * N_];
__device__ float g_WrT[N_ * N_];
__device__ float g_WpP[G_ * N_];       // gate-packed p_Whh  (row n*3+g)
__device__ float g_bpP[G_];
__device__ float g_WpH[G_ * N_];       // gate-packed h_Whh
__device__ float g_bpH[G_];
__device__ float g_WpM[G_ * N_];       // gate-packed m_Whh
__device__ float g_bpM[G_];
__device__ float g_AihP[G_ * N_];      // gate-packed m_Wih[:, 0:512]
__device__ float g_mWihH[G_ * N_];     // m_Wih[:, 512:1024] (natural gate order)

// ------------------------------- math helpers ------------------------------
__device__ __forceinline__ float sigm_f(float x) {
    return 1.0f / (1.0f + __expf(-x));
}
__device__ __forceinline__ float tanh_f(float x) {
    float e = __expf(-2.0f * fabsf(x));
    float t = (1.0f - e) / (1.0f + e);
    return copysignf(t, x);
}

// ------------------------------- prep kernels ------------------------------
__global__ void make_masks_k(const int* __restrict__ prem,
                             const int* __restrict__ hyp) {
    int i = blockIdx.x * blockDim.x + threadIdx.x;   // i = t*B + b
    if (i < T_ * B_) {
        int t = i >> 7, b = i & 127;
        g_maskP[i] = (prem[b * T_ + t] != 0) ? 1.0f : 0.0f;
        g_maskH[i] = (hyp [b * T_ + t] != 0) ? 1.0f : 0.0f;
    }
}

__global__ void zero_state_k() {
    int i = blockIdx.x * blockDim.x + threadIdx.x;
    if (i < B_ * N_) { g_h0[i] = 0.0f; g_r0[i] = 0.0f; }
}

__global__ void transpose512_k(const float* __restrict__ src,
                               float* __restrict__ dst) {
    int i = blockIdx.x * blockDim.x + threadIdx.x;
    if (i < N_ * N_) {
        int r = i >> 9, c = i & 511;
        dst[c * N_ + r] = src[i];
    }
}

// Wp[(n*3+g)*512 + k] = W[(g*512+n)*ld + coloff + k]
__global__ void pack_gate_k(const float* __restrict__ W,
                            const float* __restrict__ b,
                            float* __restrict__ Wp, float* __restrict__ bp,
                            int ld, int coloff) {
    int i = blockIdx.x * blockDim.x + threadIdx.x;
    if (i < G_ * N_) {
        int j = i >> 9;
        int k = i & 511;
        int n = j / 3, g = j - n * 3;
        Wp[i] = W[(size_t)(g * N_ + n) * ld + coloff + k];
        if (k == 0 && bp) bp[j] = b[g * N_ + n];
    }
}

__global__ void split_mwih_h_k(const float* __restrict__ mWih,
                               float* __restrict__ out) {
    int i = blockIdx.x * blockDim.x + threadIdx.x;
    if (i < G_ * N_) {
        int j = i >> 9, k = i & 511;
        out[i] = mWih[(size_t)j * 1024 + 512 + k];
    }
}

// ------------------------------- big GEMM ----------------------------------
// C[M,N] = Aeff @ Bt^T (+bias[n]) ; Aeff row m = gidx ? A[tok(m)] : A[m]
// tok(m) = gidx[(m%128)*128 + m/128]  (embedding gather fused)
// Tiles: 128x128, TK=16, 256 threads, 8x8 micro-tile.
__global__ void gemm_big_k(const float* __restrict__ A,
                           const int*   __restrict__ gidx,
                           const float* __restrict__ Bt,
                           const float* __restrict__ bias,
                           float* __restrict__ C,
                           int M, int N, int K) {
    __shared__ float As[16][132];
    __shared__ float Bs[16][132];
    int tid = threadIdx.x;
    int tx = tid & 15, ty = tid >> 4;
    int m0 = blockIdx.y * 128, n0 = blockIdx.x * 128;

    float acc[8][8];
#pragma unroll
    for (int i = 0; i < 8; i++)
#pragma unroll
        for (int j = 0; j < 8; j++) acc[i][j] = 0.0f;

    int arow = m0 + (tid >> 1);
    const float* abase;
    if (gidx) {
        int tok = gidx[(arow & 127) * 128 + (arow >> 7)];
        abase = A + (size_t)tok * K;
    } else {
        abase = A + (size_t)arow * K;
    }
    int brow = n0 + (tid >> 1);
    const float* bbase = Bt + (size_t)brow * K;
    int kk = (tid & 1) * 8;

    for (int k0 = 0; k0 < K; k0 += 16) {
#pragma unroll
        for (int i = 0; i < 8; i++) {
            int k = k0 + kk + i;
            As[kk + i][tid >> 1] = (k < K) ? abase[k] : 0.0f;
            Bs[kk + i][tid >> 1] = (k < K) ? bbase[k] : 0.0f;
        }
        __syncthreads();
#pragma unroll
        for (int k = 0; k < 16; k++) {
            float a[8], b[8];
#pragma unroll
            for (int i = 0; i < 8; i++) a[i] = As[k][ty * 8 + i];
#pragma unroll
            for (int j = 0; j < 8; j++) b[j] = Bs[k][tx * 8 + j];
#pragma unroll
            for (int i = 0; i < 8; i++)
#pragma unroll
                for (int j = 0; j < 8; j++) acc[i][j] += a[i] * b[j];
        }
        __syncthreads();
    }
#pragma unroll
    for (int i = 0; i < 8; i++) {
        int row = m0 + ty * 8 + i;
        if (row >= M) continue;
#pragma unroll
        for (int j = 0; j < 8; j++) {
            int col = n0 + tx * 8 + j;
            if (col >= N) continue;
            float v = acc[i][j];
            if (bias) v += bias[col];
            C[(size_t)row * N + col] = v;
        }
    }
}

// ------------------------------- small GEMM --------------------------------
// C[M,N] = A @ Bt^T (+bias[n]) (+addend[m][n]) ; tiles 32x64, 128 threads.
__global__ void gemm_small_k(const float* __restrict__ A,
                             const float* __restrict__ Bt,
                             const float* __restrict__ bias,
                             const float* __restrict__ addend,
                             float* __restrict__ C,
                             int M, int N, int K) {
    __shared__ float As[16][36];
    __shared__ float Bs[16][68];
    int tid = threadIdx.x;
    int tx = tid & 15, ty = tid >> 4;
    int m0 = blockIdx.y * 32, n0 = blockIdx.x * 64;

    float acc[4][4];
#pragma unroll
    for (int i = 0; i < 4; i++)
#pragma unroll
        for (int j = 0; j < 4; j++) acc[i][j] = 0.0f;

    for (int k0 = 0; k0 < K; k0 += 16) {
        {
            int r = tid >> 2, kq = (tid & 3) * 4;
            const float* ap = A + (size_t)(m0 + r) * K + k0 + kq;
#pragma unroll
            for (int i = 0; i < 4; i++) {
                int k = k0 + kq + i;
                As[kq + i][r] = (k < K) ? ap[i] : 0.0f;
            }
        }
        {
            int r = tid >> 1, kq = (tid & 1) * 8;
            const float* bp = Bt + (size_t)(n0 + r) * K + k0 + kq;
#pragma unroll
            for (int i = 0; i < 8; i++) {
                int k = k0 + kq + i;
                Bs[kq + i][r] = (k < K) ? bp[i] : 0.0f;
            }
        }
        __syncthreads();
#pragma unroll
        for (int k = 0; k < 16; k++) {
            float a[4], b[4];
#pragma unroll
            for (int i = 0; i < 4; i++) a[i] = As[k][ty * 4 + i];
#pragma unroll
            for (int j = 0; j < 4; j++) b[j] = Bs[k][tx * 4 + j];
#pragma unroll
            for (int i = 0; i < 4; i++)
#pragma unroll
                for (int j = 0; j < 4; j++) acc[i][j] += a[i] * b[j];
        }
        __syncthreads();
    }
#pragma unroll
    for (int i = 0; i < 4; i++) {
        int row = m0 + ty * 4 + i;
        if (row >= M) continue;
#pragma unroll
        for (int j = 0; j < 4; j++) {
            int col = n0 + tx * 4 + j;
            if (col >= N) continue;
            float v = acc[i][j];
            if (bias)   v += bias[col];
            if (addend) v += addend[(size_t)row * N + col];
            C[(size_t)row * N + col] = v;
        }
    }
}

// ------------------------------- fused GRU step ----------------------------
// gh = h_prev @ Wpack^T + bpack (gate-packed rows n*3+g), then gate math +
// masked h/o update. Grid: (N/16, B/32) = (32,4), 128 threads.
__global__ void gru_step_k(const float* __restrict__ Gi_t,     // [B][1536]
                           const float* __restrict__ h_prev,   // [B][512]
                           const float* __restrict__ o_prev,   // [B][512] | null
                           const float* __restrict__ Wpack,    // [1536][512]
                           const float* __restrict__ bpack,    // [1536]
                           const float* __restrict__ mask_t,   // [B]
                           float* __restrict__ h_out,
                           float* __restrict__ o_out,
                           int first) {
    __shared__ float Hs[16][36];
    __shared__ float Ws[16][50];
    int tid = threadIdx.x;
    int n0 = blockIdx.x * 16, b0 = blockIdx.y * 32;
    int j0 = n0 * 3;
    int tx = tid & 15, ty = tid >> 4;

    float acc[4][3];
#pragma unroll
    for (int i = 0; i < 4; i++)
#pragma unroll
        for (int g = 0; g < 3; g++) acc[i][g] = 0.0f;

    for (int k0 = 0; k0 < N_; k0 += 16) {
        {
            int bl = tid >> 2, kq = (tid & 3) * 4;
            const float* hp = h_prev + (size_t)(b0 + bl) * N_ + k0 + kq;
#pragma unroll
            for (int i = 0; i < 4; i++) Hs[kq + i][bl] = hp[i];
        }
#pragma unroll
        for (int rr = 0; rr < 6; rr++) {
            int e = tid + rr * 128;
            int jl = e >> 4, kq = e & 15;
            Ws[kq][jl] = Wpack[(size_t)(j0 + jl) * N_ + k0 + kq];
        }
        __syncthreads();
#pragma unroll
        for (int k = 0; k < 16; k++) {
            float h[4], w[3];
#pragma unroll
            for (int i = 0; i < 4; i++) h[i] = Hs[k][ty * 4 + i];
#pragma unroll
            for (int g = 0; g < 3; g++) w[g] = Ws[k][tx * 3 + g];
#pragma unroll
            for (int i = 0; i < 4; i++)
#pragma unroll
                for (int g = 0; g < 3; g++) acc[i][g] += h[i] * w[g];
        }
        __syncthreads();
    }
    int n = n0 + tx;
    float br = bpack[j0 + tx * 3 + 0];
    float bz = bpack[j0 + tx * 3 + 1];
    float bn = bpack[j0 + tx * 3 + 2];
#pragma unroll
    for (int i = 0; i < 4; i++) {
        int b = b0 + ty * 4 + i;
        float gir = Gi_t[(size_t)b * G_ + n];
        float giz = Gi_t[(size_t)b * G_ + 512 + n];
        float gin = Gi_t[(size_t)b * G_ + 1024 + n];
        float rg = sigm_f(gir + acc[i][0] + br);
        float zg = sigm_f(giz + acc[i][1] + bz);
        float nn = tanh_f(gin + rg * (acc[i][2] + bn));
        float hp = h_prev[(size_t)b * N_ + n];
        float hr = (1.0f - zg) * nn + zg * hp;
        float m = mask_t[b];
        h_out[(size_t)b * N_ + n] = hr * m + hp * (1.0f - m);
        o_out[(size_t)b * N_ + n] =
            first ? hr : (hr * m + o_prev[(size_t)b * N_ + n] * (1.0f - m));
    }
}

// ------------------------------- attention: alpha --------------------------
// alpha[b][t'] = sum_n tanh(Yw[t'][b][n] + s[b][n]) * Walpha[n] - 1000*(1-mP)
// One warp per (b,t'); 2048 blocks x 256 threads.
__global__ void attn_alpha_k(const float* __restrict__ Walpha) {
    int gw = (blockIdx.x * blockDim.x + threadIdx.x) >> 5;
    int lane = threadIdx.x & 31;
    if (gw >= B_ * T_) return;
    int b = gw >> 7, tp = gw & 127;
    const float* yw = g_Yw + ((size_t)tp * B_ + b) * N_;
    const float* sb = g_s + (size_t)b * N_;
    float acc = 0.0f;
#pragma unroll 4
    for (int n = lane; n < N_; n += 32)
        acc += tanh_f(yw[n] + sb[n]) * Walpha[n];
#pragma unroll
    for (int o = 16; o; o >>= 1) acc += __shfl_xor_sync(0xffffffffu, acc, o);
    if (lane == 0)
        g_alpha[b * T_ + tp] = acc - 1000.0f * (1.0f - g_maskP[tp * B_ + b]);
}

// ------------------------------- attention: softmax + context --------------
// One block per b. softmax over t', then a[b][n] = sum_t' w[t'] * Y[t'][b][n].
__global__ void attn_ctx_k() {
    __shared__ float w[T_];
    int b = blockIdx.x, tid = threadIdx.x;
    if (tid < T_) w[tid] = g_alpha[b * T_ + tid];
    __syncthreads();
    if (tid < 32) {
        float mx = -1e30f;
        for (int t = tid; t < T_; t += 32) mx = fmaxf(mx, w[t]);
#pragma unroll
        for (int o = 16; o; o >>= 1)
            mx = fmaxf(mx, __shfl_xor_sync(0xffffffffu, mx, o));
        float sm = 0.0f;
        for (int t = tid; t < T_; t += 32) {
            float e = __expf(w[t] - mx);
            w[t] = e;
            sm += e;
        }
#pragma unroll
        for (int o = 16; o; o >>= 1) sm += __shfl_xor_sync(0xffffffffu, sm, o);
        float inv = 1.0f / sm;
        for (int t = tid; t < T_; t += 32) w[t] *= inv;
    }
    __syncthreads();
    for (int n = tid; n < N_; n += blockDim.x) {
        float acc = 0.0f;
#pragma unroll 4
        for (int t = 0; t < T_; t++)
            acc += w[t] * g_oP[((size_t)t * B_ + b) * N_ + n];
        g_a[(size_t)b * N_ + n] = acc;
    }
}

// ------------------------------- fused match-GRU step ----------------------
// gi = gihp[t] + a @ AihP^T ; gh = r @ WpM^T + bpM ; gate math ; masked r.
__global__ void match_step_k(const float* __restrict__ gihp_t,  // [B][1536]
                             const float* __restrict__ a_in,    // [B][512]
                             const float* __restrict__ r_prev,  // [B][512]
                             const float* __restrict__ mask_t,  // [B]
                             float* __restrict__ r_out) {
    __shared__ float As[16][36];
    __shared__ float Rs[16][36];
    __shared__ float WA[16][50];
    __shared__ float WR[16][50];
    int tid = threadIdx.x;
    int n0 = blockIdx.x * 16, b0 = blockIdx.y * 32;
    int j0 = n0 * 3;
    int tx = tid & 15, ty = tid >> 4;

    float accA[4][3], accR[4][3];
#pragma unroll
    for (int i = 0; i < 4; i++)
#pragma unroll
        for (int g = 0; g < 3; g++) { accA[i][g] = 0.0f; accR[i][g] = 0.0f; }

    for (int k0 = 0; k0 < N_; k0 += 16) {
        {
            int bl = tid >> 2, kq = (tid & 3) * 4;
            const float* ap = a_in   + (size_t)(b0 + bl) * N_ + k0 + kq;
            const float* rp = r_prev + (size_t)(b0 + bl) * N_ + k0 + kq;
#pragma unroll
            for (int i = 0; i < 4; i++) {
                As[kq + i][bl] = ap[i];
                Rs[kq + i][bl] = rp[i];
            }
        }
#pragma unroll
        for (int rr = 0; rr < 6; rr++) {
            int e = tid + rr * 128;
            int jl = e >> 4, kq = e & 15;
            WA[kq][jl] = g_AihP[(size_t)(j0 + jl) * N_ + k0 + kq];
            WR[kq][jl] = g_WpM [(size_t)(j0 + jl) * N_ + k0 + kq];
        }
        __syncthreads();
#pragma unroll
        for (int k = 0; k < 16; k++) {
            float av[4], rv[4], wa[3], wr[3];
#pragma unroll
            for (int i = 0; i < 4; i++) {
                av[i] = As[k][ty * 4 + i];
                rv[i] = Rs[k][ty * 4 + i];
            }
#pragma unroll
            for (int g = 0; g < 3; g++) {
                wa[g] = WA[k][tx * 3 + g];
                wr[g] = WR[k][tx * 3 + g];
            }
#pragma unroll
            for (int i = 0; i < 4; i++)
#pragma unroll
                for (int g = 0; g < 3; g++) {
                    accA[i][g] += av[i] * wa[g];
                    accR[i][g] += rv[i] * wr[g];
                }
        }
        __syncthreads();
    }
    int n = n0 + tx;
    float br = g_bpM[j0 + tx * 3 + 0];
    float bz = g_bpM[j0 + tx * 3 + 1];
    float bn = g_bpM[j0 + tx * 3 + 2];
#pragma unroll
    for (int i = 0; i < 4; i++) {
        int b = b0 + ty * 4 + i;
        float gir = gihp_t[(size_t)b * G_ + n]         + accA[i][0];
        float giz = gihp_t[(size_t)b * G_ + 512 + n]   + accA[i][1];
        float gin = gihp_t[(size_t)b * G_ + 1024 + n]  + accA[i][2];
        float rg = sigm_f(gir + accR[i][0] + br);
        float zg = sigm_f(giz + accR[i][1] + bz);
        float nn = tanh_f(gin + rg * (accR[i][2] + bn));
        float rp = r_prev[(size_t)b * N_ + n];
        float rr = (1.0f - zg) * nn + zg * rp;
        float m = mask_t[b];
        r_out[(size_t)b * N_ + n] = rr * m + rp * (1.0f - m);
    }
}

// ------------------------------- logits + log_softmax ----------------------
__global__ void logits_k(const float* __restrict__ r,
                         const float* __restrict__ W,   // [3][512]
                         const float* __restrict__ bo,  // [3]
                         float* __restrict__ out) {
    int b = blockIdx.x, lane = threadIdx.x;
    float a0 = 0.0f, a1 = 0.0f, a2 = 0.0f;
    for (int k = lane; k < N_; k += 32) {
        float rv = r[(size_t)b * N_ + k];
        a0 += rv * W[k];
        a1 += rv * W[512 + k];
        a2 += rv * W[1024 + k];
    }
#pragma unroll
    for (int o = 16; o; o >>= 1) {
        a0 += __shfl_xor_sync(0xffffffffu, a0, o);
        a1 += __shfl_xor_sync(0xffffffffu, a1, o);
        a2 += __shfl_xor_sync(0xffffffffu, a2, o);
    }
    if (lane == 0) {
        float l0 = a0 + bo[0], l1 = a1 + bo[1], l2 = a2 + bo[2];
        float mx = fmaxf(l0, fmaxf(l1, l2));
        float s = __expf(l0 - mx) + __expf(l1 - mx) + __expf(l2 - mx);
        float lg = mx + logf(s);
        out[b * 3 + 0] = l0 - lg;
        out[b * 3 + 1] = l1 - lg;
        out[b * 3 + 2] = l2 - lg;
    }
}

// ---------------------------------------------------------------------------
extern "C" void kernel_launch(void* const* d_in, const int* in_sizes, int n_in,
                              void* d_out, int out_size) {
    const int*   prem   = (const int*)  d_in[0];
    const int*   hyp    = (const int*)  d_in[1];
    const float* E      = (const float*)d_in[2];
    const float* p_Wih  = (const float*)d_in[3];
    const float* p_Whh  = (const float*)d_in[4];
    const float* p_bih  = (const float*)d_in[5];
    const float* p_bhh  = (const float*)d_in[6];
    const float* h_Wih  = (const float*)d_in[7];
    const float* h_Whh  = (const float*)d_in[8];
    const float* h_bih  = (const float*)d_in[9];
    const float* h_bhh  = (const float*)d_in[10];
    const float* m_Wih  = (const float*)d_in[11];
    const float* m_Whh  = (const float*)d_in[12];
    const float* m_bih  = (const float*)d_in[13];
    const float* m_bhh  = (const float*)d_in[14];
    const float* W_y    = (const float*)d_in[15];
    const float* W_h    = (const float*)d_in[16];
    const float* W_r    = (const float*)d_in[17];
    const float* W_alpha= (const float*)d_in[18];
    const float* out_W  = (const float*)d_in[19];
    const float* out_b  = (const float*)d_in[20];
    float* out = (float*)d_out;

    float *GiP, *GiH, *oP, *oH, *Yw, *hWh, *gihp;
    float *h0, *h1, *r0, *r1, *sP, *aP;
    float *WyT, *WhT, *WrT, *WpP, *bpP, *WpH, *bpH, *WpM, *bpM, *AihP, *mWihH;
    float *maskP, *maskH;
    cudaGetSymbolAddress((void**)&GiP,  g_GiP);
    cudaGetSymbolAddress((void**)&GiH,  g_GiH);
    cudaGetSymbolAddress((void**)&oP,   g_oP);
    cudaGetSymbolAddress((void**)&oH,   g_oH);
    cudaGetSymbolAddress((void**)&Yw,   g_Yw);
    cudaGetSymbolAddress((void**)&hWh,  g_hWh);
    cudaGetSymbolAddress((void**)&gihp, g_gihp);
    cudaGetSymbolAddress((void**)&h0,   g_h0);
    cudaGetSymbolAddress((void**)&h1,   g_h1);
    cudaGetSymbolAddress((void**)&r0,   g_r0);
    cudaGetSymbolAddress((void**)&r1,   g_r1);
    cudaGetSymbolAddress((void**)&sP,   g_s);
    cudaGetSymbolAddress((void**)&aP,   g_a);
    cudaGetSymbolAddress((void**)&WyT,  g_WyT);
    cudaGetSymbolAddress((void**)&WhT,  g_WhT);
    cudaGetSymbolAddress((void**)&WrT,  g_WrT);
    cudaGetSymbolAddress((void**)&WpP,  g_WpP);
    cudaGetSymbolAddress((void**)&bpP,  g_bpP);
    cudaGetSymbolAddress((void**)&WpH,  g_WpH);
    cudaGetSymbolAddress((void**)&bpH,  g_bpH);
    cudaGetSymbolAddress((void**)&WpM,  g_WpM);
    cudaGetSymbolAddress((void**)&bpM,  g_bpM);
    cudaGetSymbolAddress((void**)&AihP, g_AihP);
    cudaGetSymbolAddress((void**)&mWihH,g_mWihH);
    cudaGetSymbolAddress((void**)&maskP,g_maskP);
    cudaGetSymbolAddress((void**)&maskH,g_maskH);

    // ---- prep ----
    make_masks_k<<<64, 256>>>(prem, hyp);
    zero_state_k<<<256, 256>>>();
    transpose512_k<<<1024, 256>>>(W_y, WyT);
    transpose512_k<<<1024, 256>>>(W_h, WhT);
    transpose512_k<<<1024, 256>>>(W_r, WrT);
    pack_gate_k<<<3072, 256>>>(p_Whh, p_bhh, WpP, bpP, 512, 0);
    pack_gate_k<<<3072, 256>>>(h_Whh, h_bhh, WpH, bpH, 512, 0);
    pack_gate_k<<<3072, 256>>>(m_Whh, m_bhh, WpM, bpM, 512, 0);
    pack_gate_k<<<3072, 256>>>(m_Wih, nullptr, AihP, nullptr, 1024, 0);
    split_mwih_h_k<<<3072, 256>>>(m_Wih, mWihH);

    // ---- input-gate precompute (gather fused) ----
    dim3 gGi(G_ / 128, TBN_ / 128);   // (12, 128)
    gemm_big_k<<<gGi, 256>>>(E, prem, p_Wih, p_bih, GiP, TBN_, G_, E_);
    gemm_big_k<<<gGi, 256>>>(E, hyp,  h_Wih, h_bih, GiH, TBN_, G_, E_);

    // ---- premise GRU ----
    float* hb[2] = {h0, h1};
    int cur = 0;
    for (int t = 0; t < T_; t++) {
        gru_step_k<<<dim3(32, 4), 128>>>(
            GiP + (size_t)t * B_ * G_, hb[cur],
            t ? (oP + (size_t)(t - 1) * B_ * N_) : nullptr,
            WpP, bpP, maskP + t * B_,
            hb[cur ^ 1], oP + (size_t)t * B_ * N_, t == 0);
        cur ^= 1;
    }
    // ---- hypothesis GRU (h0 = premise final h, keeps ping-pong) ----
    for (int t = 0; t < T_; t++) {
        gru_step_k<<<dim3(32, 4), 128>>>(
            GiH + (size_t)t * B_ * G_, hb[cur],
            t ? (oH + (size_t)(t - 1) * B_ * N_) : nullptr,
            WpH, bpH, maskH + t * B_,
            hb[cur ^ 1], oH + (size_t)t * B_ * N_, t == 0);
        cur ^= 1;
    }

    // ---- attention precompute ----
    gemm_big_k<<<dim3(N_ / 128, TBN_ / 128), 256>>>(oP, nullptr, WyT, nullptr,
                                                    Yw, TBN_, N_, N_);
    gemm_big_k<<<dim3(N_ / 128, TBN_ / 128), 256>>>(oH, nullptr, WhT, nullptr,
                                                    hWh, TBN_, N_, N_);
    gemm_big_k<<<dim3(G_ / 128, TBN_ / 128), 256>>>(oH, nullptr, mWihH, m_bih,
                                                    gihp, TBN_, G_, N_);

    // ---- attention loop ----
    float* rb[2] = {r0, r1};
    int rc = 0;
    for (int t = 0; t < T_; t++) {
        // s = r @ W_r + hWh[t]
        gemm_small_k<<<dim3(8, 4), 128>>>(rb[rc], WrT, nullptr,
                                          hWh + (size_t)t * B_ * N_,
                                          sP, B_, N_, N_);
        attn_alpha_k<<<2048, 256>>>(W_alpha);
        attn_ctx_k<<<128, 256>>>();
        match_step_k<<<dim3(32, 4), 128>>>(gihp + (size_t)t * B_ * G_,
                                           aP, rb[rc], maskH + t * B_,
                                           rb[rc ^ 1]);
        rc ^= 1;
    }

    // ---- classifier ----
    logits_k<<<128, 32>>>(rb[rc], out_W, out_b, out);
    (void)in_sizes; (void)n_in; (void)out_size;
}